// round 13
// baseline (speedup 1.0000x reference)
#include <cuda_runtime.h>

// T=256, BS=128, N=2048. One persistent CTA per batch lane.
// Warp-specialized: warp0 = scalar-chain owner (5 pairs/lane); warps1-3 = 9 pairs/lane.
#define T_STEPS 256
#define BSZ     128
#define NFEAT   2048
#define BLOCK   128
#define NWARP   4
#define NPART   16
#define FUDGE_C 1e-4f
#define NP0     5
#define NP1     9

typedef unsigned long long ull;

static __device__ __forceinline__ ull pack2(float lo, float hi) {
    ull r; asm("mov.b64 %0, {%1, %2};" : "=l"(r) : "f"(lo), "f"(hi)); return r;
}
static __device__ __forceinline__ ull bcast2(float v) { return pack2(v, v); }
static __device__ __forceinline__ float2 unpack2(ull v) {
    float2 r; asm("mov.b64 {%0, %1}, %2;" : "=f"(r.x), "=f"(r.y) : "l"(v)); return r;
}
static __device__ __forceinline__ ull fma2(ull a, ull b, ull c) {
    ull d; asm("fma.rn.f32x2 %0, %1, %2, %3;" : "=l"(d) : "l"(a), "l"(b), "l"(c)); return d;
}
static __device__ __forceinline__ ull add2(ull a, ull b) {
    ull d; asm("add.rn.f32x2 %0, %1, %2;" : "=l"(d) : "l"(a), "l"(b)); return d;
}
static __device__ __forceinline__ ull relu2(ull v) {
    float2 f = unpack2(v);
    return pack2(fmaxf(f.x, 0.0f), fmaxf(f.y, 0.0f));
}

struct Shm {
    float  s_y[T_STEPS];
    float  s_n[T_STEPS];
    float  s_q[T_STEPS];
    ull    s_p[2][NPART];     // double-buffered packed (au,ah) partials
    float4 s_c[2][2];         // double-buffered coefs: {aec,be,belp,lic},{axc,bx,-,-}
};

struct Par {
    float lr0, lrd, osc, ufsm1, spwd, qsc;
    float itq, ctq, ity, cty, ite, cte;
};

template<int NP>
static __device__ __forceinline__ void body(
    Shm* sm, const float* __restrict__ w_in, const float* __restrict__ w_inq,
    const float* __restrict__ zb, float* __restrict__ out,
    int b, int wid, int lane, Par p, float sigb)
{
    const int wb = (NP == NP0) ? 0 : (160 + (wid - 1) * 288);   // pair base

    ull win2[NP], wiq2[NP], bia2[NP], W2[NP], A2[NP], hv[NP];
    {
        const float2* wi2 = reinterpret_cast<const float2*>(w_in);
        const float2* wq2 = reinterpret_cast<const float2*>(w_inq);
        const float2* zb2 = reinterpret_cast<const float2*>(zb);
        #pragma unroll
        for (int k = 0; k < NP; ++k) {
            const int idx = wb + k * 32 + lane;
            float2 a = wi2[idx], c = wq2[idx], z = zb2[idx];
            win2[k] = pack2(a.x, a.y);
            wiq2[k] = pack2(c.x, c.y);
            bia2[k] = pack2(sigb * z.x, sigb * z.y);
            W2[k]   = 0ull;
        }
    }

    // ---------------- Prologue: step-0 partials ----------------
    float qlp = sm->s_q[0] * p.itq;
    {
        const ull x2  = bcast2(sm->s_n[0]);                // x_0 = noise_0
        const ull cq2 = bcast2(p.qsc * qlp);
        ull ah0 = 0ull, ah1 = 0ull;
        #pragma unroll
        for (int k = 0; k < NP; ++k) {
            ull h = relu2(fma2(win2[k], x2, fma2(cq2, wiq2[k], bia2[k])));
            hv[k] = h;
            if (k & 1) ah1 = fma2(h, h, ah1); else ah0 = fma2(h, h, ah0);
        }
        float2 f = unpack2(add2(ah0, ah1));
        float ah_s = f.x + f.y;
        float au_s = 0.0f;
        #pragma unroll
        for (int off = 16; off >= 4; off >>= 1) {
            au_s += __shfl_xor_sync(0xFFFFFFFFu, au_s, off);
            ah_s += __shfl_xor_sync(0xFFFFFFFFu, ah_s, off);
        }
        if (lane < 4) sm->s_p[0][(wid << 2) | lane] = pack2(au_s, ah_s);
    }

    // Warp0-only scalar state + iteration-0 coefficients.
    float lrmult = 1.0f, ylp = 0.0f;
    float lr_c = p.lr0, cW = 1.0f, cWn = 0.0f, icWn = 0.0f;
    float y_c = 0.0f, byl_c = 0.0f;
    bool  flag_c = false;
    if (NP == NP0) {
        cWn  = fmaf(-lr_c, p.spwd, 1.0f);
        icWn = __fdividef(1.0f, cWn);
        y_c    = sm->s_y[0];
        flag_c = ((__float_as_uint(y_c) & 0x7FFFFFFFu) > 0x7F800000u);
        const float aec = (flag_c ? (p.ity - 1.0f) : -1.0f);    // cW = 1
        const float be  = flag_c ? 0.0f : p.ity * y_c;
        const float lic = lr_c * icWn;
        const float axc = p.ufsm1 + (flag_c ? p.ity : 0.0f);
        const float bx  = be + sm->s_n[1];
        if (lane == 0) {
            sm->s_c[0][0] = make_float4(aec, be, 0.0f, lic);
            sm->s_c[0][1] = make_float4(axc, bx, 0.0f, 0.0f);
        }
    }
    qlp = fmaf(p.ctq, qlp, sm->s_q[1] * p.itq);
    ull cq2_c = bcast2(p.qsc * qlp);

    __syncthreads();   // s_p[0], s_c[0] visible

    #pragma unroll 2
    for (int t = 0; t < T_STEPS; ++t) {
        const int buf = t & 1;

        // --- Post-bar top: coefs + partials LDS; A2 prep fills the wait. ---
        const float4 c0 = sm->s_c[buf][0];   // {aec, be, belp, lic}
        const float4 c1 = sm->s_c[buf][1];   // {axc, bx, -, -}
        const longlong2* pp = reinterpret_cast<const longlong2*>(sm->s_p[buf]);
        longlong2 l0 = pp[0], l1 = pp[1], l2 = pp[2], l3 = pp[3];
        longlong2 l4 = pp[4], l5 = pp[5], l6 = pp[6], l7 = pp[7];

        #pragma unroll
        for (int k = 0; k < NP; ++k) A2[k] = fma2(cq2_c, wiq2[k], bia2[k]);

        ull r0 = add2(add2((ull)l0.x, (ull)l0.y), add2((ull)l1.x, (ull)l1.y));
        ull r1 = add2(add2((ull)l2.x, (ull)l2.y), add2((ull)l3.x, (ull)l3.y));
        ull r2 = add2(add2((ull)l4.x, (ull)l4.y), add2((ull)l5.x, (ull)l5.y));
        ull r3 = add2(add2((ull)l6.x, (ull)l6.y), add2((ull)l7.x, (ull)l7.y));
        float2 s = unpack2(add2(add2(r0, r1), add2(r2, r3)));
        const float sumu = s.x, sumh = s.y;

        // --- Short affine chains off sumu (coefs from warp0's previous tail). ---
        const float en   = fmaf(c0.x, sumu, c0.y);            // e_t
        const float elpn = fmaf(p.ite, en, c0.z);             // elp_t
        const ull leoc2  = bcast2(c0.w * elpn);               // W-update coeff
        const ull x2     = bcast2(fmaf(c1.x, sumu, c1.y));    // x_{t+1}

        // --- Hot loop: W_{t+1}, h_{t+1}, partial dot/sumsq. ---
        ull au0 = 0ull, au1 = 0ull, ah0 = 0ull, ah1 = 0ull;
        #pragma unroll
        for (int k = 0; k < NP; ++k) {
            W2[k] = fma2(leoc2, hv[k], W2[k]);
            ull h = relu2(fma2(win2[k], x2, A2[k]));
            hv[k] = h;
            if (k & 1) { au1 = fma2(W2[k], h, au1); ah1 = fma2(h, h, ah1); }
            else       { au0 = fma2(W2[k], h, au0); ah0 = fma2(h, h, ah0); }
        }
        float2 auf = unpack2(add2(au0, au1));
        float2 ahf = unpack2(add2(ah0, ah1));
        float au_s = auf.x + auf.y;
        float ah_s = ahf.x + ahf.y;

        // --- 3-level butterfly; lanes 0-3 hold the 4 residue classes. ---
        #pragma unroll
        for (int off = 16; off >= 4; off >>= 1) {
            au_s += __shfl_xor_sync(0xFFFFFFFFu, au_s, off);
            ah_s += __shfl_xor_sync(0xFFFFFFFFu, ah_s, off);
        }

        // --- Warp0-only tail (fits its shfl shadow; other warps skip). ---
        if (NP == NP0) {
            const float un = cW * sumu;                        // u_t
            if (lane == 0) out[t * BSZ + b] = p.osc * un;
            const float ysel = flag_c ? un : y_c;
            ylp = fmaf(p.ity, ysel, byl_c);
            const float le = lr_c * elpn;
            const float v  = fmaf(le * le, sumh, FUDGE_C);
            lrmult *= __expf(-p.lrd * (v * __frsqrt_rn(v)));   // exp(-lrd*sqrt(v))
            lr_c = p.lr0 * lrmult;                             // lr_{t+1}
            cW   = cWn;                                        // cW_{t+1}
            cWn  = cW * fmaf(-lr_c, p.spwd, 1.0f);             // cW_{t+2}
            icWn = __fdividef(1.0f, cWn);
            const int ti = (t + 1 < T_STEPS) ? (t + 1) : t;
            const int tn = (t + 2 < T_STEPS) ? (t + 2) : (T_STEPS - 1);
            y_c    = sm->s_y[ti];
            flag_c = ((__float_as_uint(y_c) & 0x7FFFFFFFu) > 0x7F800000u);
            byl_c  = p.cty * ylp;
            const float axc = (p.ufsm1 + (flag_c ? p.ity : 0.0f)) * cW;
            const float be  = (flag_c ? 0.0f : p.ity * y_c) + byl_c;
            const float bx  = be + sm->s_n[tn];
            const float aec = (flag_c ? (p.ity - 1.0f) : -1.0f) * cW;
            const float belp = p.cte * elpn;
            const float lic  = lr_c * icWn;
            if (lane == 0) {
                sm->s_c[buf ^ 1][0] = make_float4(aec, be, belp, lic);
                sm->s_c[buf ^ 1][1] = make_float4(axc, bx, 0.0f, 0.0f);
            }
        }

        // --- All warps: qlp chain (cheap, local) + partial STS; then bar. ---
        {
            const int tn = (t + 2 < T_STEPS) ? (t + 2) : (T_STEPS - 1);
            qlp   = fmaf(p.ctq, qlp, sm->s_q[tn] * p.itq);
            cq2_c = bcast2(p.qsc * qlp);
        }
        if (lane < 4) sm->s_p[buf ^ 1][(wid << 2) | lane] = pack2(au_s, ah_s);
        __syncthreads();
    }
}

__global__ __launch_bounds__(BLOCK, 1)
void elbo_scan_kernel(const float* __restrict__ noises,
                      const float* __restrict__ ys,
                      const float* __restrict__ qs,
                      const float* __restrict__ z_biases,
                      const float* __restrict__ w_in,
                      const float* __restrict__ w_inq,
                      const float* __restrict__ p_llr,
                      const float* __restrict__ p_llrd,
                      const float* __restrict__ p_sigb,
                      const float* __restrict__ p_os,
                      const float* __restrict__ p_ufs,
                      const float* __restrict__ p_spwd,
                      const float* __restrict__ p_qsc,
                      const float* __restrict__ p_tq,
                      const float* __restrict__ p_ty,
                      const float* __restrict__ p_te,
                      float* __restrict__ out)
{
    __shared__ Shm sm;
    const int b    = blockIdx.x;
    const int tid  = threadIdx.x;
    const int wid  = tid >> 5;
    const int lane = tid & 31;

    sm.s_y[tid]         = ys[tid * BSZ + b];
    sm.s_y[tid + BLOCK] = ys[(tid + BLOCK) * BSZ + b];
    sm.s_n[tid]         = noises[tid * BSZ + b];
    sm.s_n[tid + BLOCK] = noises[(tid + BLOCK) * BSZ + b];
    sm.s_q[tid]         = qs[tid * BSZ + b];
    sm.s_q[tid + BLOCK] = qs[(tid + BLOCK) * BSZ + b];

    Par p;
    p.lr0   = expf(p_llr[0]);
    p.lrd   = expf(p_llrd[0]);
    p.osc   = p_os[0];
    p.ufsm1 = p_ufs[0] - 1.0f;
    p.spwd  = log1pf(expf(p_spwd[0]));
    p.qsc   = p_qsc[0];
    const float sigb = p_sigb[0];
    const float tq = 1.0f + log1pf(expf(p_tq[0]));
    const float ty = 1.0f + log1pf(expf(p_ty[0]));
    const float te = 1.0f + log1pf(expf(p_te[0]));
    p.itq = 1.0f / tq; p.ctq = 1.0f - p.itq;
    p.ity = 1.0f / ty; p.cty = 1.0f - p.ity;
    p.ite = 1.0f / te; p.cte = 1.0f - p.ite;

    __syncthreads();   // staged inputs visible

    if (wid == 0) body<NP0>(&sm, w_in, w_inq, z_biases, out, b, wid, lane, p, sigb);
    else          body<NP1>(&sm, w_in, w_inq, z_biases, out, b, wid, lane, p, sigb);
}

extern "C" void kernel_launch(void* const* d_in, const int* in_sizes, int n_in,
                              void* d_out, int out_size)
{
    const float* noises = (const float*)d_in[1];
    const float* ys     = (const float*)d_in[2];
    const float* qs     = (const float*)d_in[3];
    const float* zb     = (const float*)d_in[4];
    const float* w_in   = (const float*)d_in[5];
    const float* w_inq  = (const float*)d_in[6];

    elbo_scan_kernel<<<BSZ, BLOCK>>>(noises, ys, qs, zb, w_in, w_inq,
                                     (const float*)d_in[7],  (const float*)d_in[8],
                                     (const float*)d_in[9],  (const float*)d_in[10],
                                     (const float*)d_in[11], (const float*)d_in[12],
                                     (const float*)d_in[13], (const float*)d_in[14],
                                     (const float*)d_in[15], (const float*)d_in[16],
                                     (float*)d_out);
}